// round 6
// baseline (speedup 1.0000x reference)
#include <cuda_runtime.h>
#include <cuda_fp16.h>
#include <math.h>
#include <cstdint>

#define N      8192
#define FH     64
#define HEADS  2
#define COUT   16
#define FIN    64
#define NW     256       // mask words per row
#define ALPHA  0.2f
#define PP     40        // smem pitch in halfs (80B: 16B-aligned, conflict-free frags+ldmatrix)

// ---------------- scratch ----------------
__device__ __align__(16) unsigned g_mask[NW * N];          // g_mask[w*N + i], bit b <-> col w*32+b
__device__ __align__(16) __half   g_WhT[HEADS][FH * N];    // transposed Wh (fp16): [f][row]
__device__ __align__(16) float    g_s1[HEADS][N];
__device__ __align__(16) float    g_s2[HEADS][N];
__device__               float    g_s2max[HEADS];
__device__ __align__(16) float    g_h[(size_t)N * (HEADS * FH)];  // [N][128] fp32
__device__ __align__(16) __half   g_WhoT[COUT * N];        // transposed Who (fp16): [c][row]
__device__ __align__(16) float    g_s1o[N];
__device__ __align__(16) float    g_s2o[N];
__device__               float    g_s2omax;

__device__ __forceinline__ uint32_t smem_u32(const void* p) {
    return (uint32_t)__cvta_generic_to_shared(p);
}

__device__ __forceinline__ void mma16816(float* c, const uint32_t* a, const uint32_t* b) {
    asm volatile("mma.sync.aligned.m16n8k16.row.col.f32.f16.f16.f32 "
        "{%0,%1,%2,%3}, {%4,%5,%6,%7}, {%8,%9}, {%0,%1,%2,%3};"
        : "+f"(c[0]), "+f"(c[1]), "+f"(c[2]), "+f"(c[3])
        : "r"(a[0]), "r"(a[1]), "r"(a[2]), "r"(a[3]), "r"(b[0]), "r"(b[1]));
}

__device__ __forceinline__ void ldm_x4(uint32_t* r, uint32_t addr) {
    asm volatile("ldmatrix.sync.aligned.m8n8.x4.shared.b16 {%0,%1,%2,%3}, [%4];"
        : "=r"(r[0]), "=r"(r[1]), "=r"(r[2]), "=r"(r[3]) : "r"(addr));
}

__device__ __forceinline__ float atomicMaxF(float* addr, float v) {
    int* ia = (int*)addr;
    int old = *ia;
    while (__int_as_float(old) < v) {
        int assumed = old;
        old = atomicCAS(ia, assumed, __float_as_int(v));
        if (old == assumed) break;
    }
    return __int_as_float(old);
}

__global__ void k0_init() {
    g_s2max[0] = -INFINITY;
    g_s2max[1] = -INFINITY;
    g_s2omax   = -INFINITY;
}

// ---------------- K1: pack adjacency into transposed bitmask (MLP=8) ----------------
__global__ void k1_pack(const int* __restrict__ adj) {
    int warp = (blockIdx.x * blockDim.x + threadIdx.x) >> 5;
    int lane = threadIdx.x & 31;
    if (warp >= N) return;
    const int* arow = adj + (size_t)warp * N;
    for (int w = 0; w < NW; w += 8) {
        int v[8];
        #pragma unroll
        for (int i = 0; i < 8; i++) v[i] = arow[(w + i) * 32 + lane];
        unsigned b[8];
        #pragma unroll
        for (int i = 0; i < 8; i++) b[i] = __ballot_sync(0xFFFFFFFFu, v[i] > 0);
        if (lane == 0) {
            #pragma unroll
            for (int i = 0; i < 8; i++) g_mask[(size_t)(w + i) * N + warp] = b[i];
        }
    }
}

// ---------------- K2: Wh = x @ W per head (stored transposed fp16), s1/s2, max(s2) ----------------
__global__ void k2_wh(const float* __restrict__ x,
                      const float* __restrict__ W_heads,
                      const float* __restrict__ a_heads) {
    int head = blockIdx.y;
    int row0 = blockIdx.x * 64;
    __shared__ float sX[64][65];
    __shared__ float sW[64][64];
    __shared__ float sA[2 * FH];
    __shared__ float sRed[2];
    int t = threadIdx.x;  // 256

    #pragma unroll
    for (int i = 0; i < 4; i++) {
        int q = t + 256 * i;
        int r = q >> 4, c = (q & 15) * 4;
        float4 v = *(const float4*)&x[(size_t)(row0 + r) * FIN + c];
        sX[r][c] = v.x; sX[r][c + 1] = v.y; sX[r][c + 2] = v.z; sX[r][c + 3] = v.w;
    }
    const float* W = W_heads + head * FIN * FH;
    #pragma unroll
    for (int i = 0; i < 4; i++) {
        int q = t + 256 * i;
        int r = q >> 4, c = (q & 15) * 4;
        *(float4*)&sW[r][c] = *(const float4*)&W[r * FH + c];
    }
    if (t < 2 * FH) sA[t] = a_heads[head * 2 * FH + t];
    __syncthreads();

    int r = t & 63, cg = t >> 6;
    float4 acc[4];
    #pragma unroll
    for (int j = 0; j < 4; j++) acc[j] = make_float4(0.f, 0.f, 0.f, 0.f);
    for (int k = 0; k < FIN; k++) {
        float xv = sX[r][k];
        #pragma unroll
        for (int j = 0; j < 4; j++) {
            float4 w4 = *(float4*)&sW[k][cg * 16 + j * 4];
            acc[j].x += xv * w4.x; acc[j].y += xv * w4.y;
            acc[j].z += xv * w4.z; acc[j].w += xv * w4.w;
        }
    }
    __syncthreads();
    #pragma unroll
    for (int j = 0; j < 4; j++) {
        sX[r][cg * 16 + j * 4 + 0] = acc[j].x;
        sX[r][cg * 16 + j * 4 + 1] = acc[j].y;
        sX[r][cg * 16 + j * 4 + 2] = acc[j].z;
        sX[r][cg * 16 + j * 4 + 3] = acc[j].w;
    }
    __syncthreads();

    if (t < 64) {
        int row = row0 + t;
        float s1 = 0.f, s2 = 0.f;
        float* o = sX[t];
        #pragma unroll
        for (int f = 0; f < FH; f++) {
            s1 += o[f] * sA[f];
            s2 += o[f] * sA[FH + f];
            g_WhT[head][(size_t)f * N + row] = __float2half(o[f]);
        }
        g_s1[head][row] = s1;
        g_s2[head][row] = s2;
        float m = s2;
        #pragma unroll
        for (int off = 16; off > 0; off >>= 1)
            m = fmaxf(m, __shfl_down_sync(0xFFFFFFFFu, m, off));
        if ((t & 31) == 0) sRed[t >> 5] = m;
    }
    __syncthreads();
    if (t == 0) atomicMaxF(&g_s2max[head], fmaxf(sRed[0], sRed[1]));
}

// ---------------- P-tile generation (vectorized s2 loads) ----------------
__device__ __forceinline__ void gen_p_tile(__half* sPb, int pr, int pg,
                                           unsigned mw, float s1v, float mv,
                                           const float* __restrict__ s2p, int j0,
                                           float& den) {
    const int kbase = pg << 4;
    float4 s2v[4];
    #pragma unroll
    for (int q = 0; q < 4; q++)
        s2v[q] = *(const float4*)(s2p + j0 + kbase + 4 * q);
    const float* s2f = (const float*)s2v;
    uint32_t packed[8];
    #pragma unroll
    for (int i = 0; i < 8; i++) {
        int k = kbase + 2 * i;
        float e0 = s1v + s2f[2 * i];
        e0 = e0 > 0.f ? e0 : ALPHA * e0;
        float p0 = ((mw >> k) & 1u) ? __expf(e0 - mv) : 0.f;
        float e1 = s1v + s2f[2 * i + 1];
        e1 = e1 > 0.f ? e1 : ALPHA * e1;
        float p1 = ((mw >> (k + 1)) & 1u) ? __expf(e1 - mv) : 0.f;
        den += p0 + p1;
        __half2 h = __floats2half2_rn(p0, p1);
        packed[i] = *(uint32_t*)&h;
    }
    uint4* dst = (uint4*)(sPb + pr * PP + kbase);
    dst[0] = make_uint4(packed[0], packed[1], packed[2], packed[3]);
    dst[1] = make_uint4(packed[4], packed[5], packed[6], packed[7]);
}

// ---------------- K4: fused masked-softmax attention GEMM (mma.sync + ldmatrix) ----------------
// BM=128, BN=64, BK=32, 256 threads. grid (64,2) = 128 blocks (single wave).
__global__ void __launch_bounds__(256) k4_attn_tc() {
    const int head = blockIdx.y;
    const int row0 = blockIdx.x * 128;
    __shared__ __align__(16) __half sP[2][128 * PP];   // 2 x 10 KB
    __shared__ __align__(16) __half sB[2][64 * PP];    // 2 x 5 KB
    __shared__ float sS1[128], sM[128], sDen[2][128];

    const int t = threadIdx.x;
    if (t < 128) {
        float v = g_s1[head][row0 + t];
        sS1[t] = v;
        float e = v + g_s2max[head];            // lrelu monotone -> valid stabilizer
        sM[t] = e > 0.f ? e : ALPHA * e;
    }
    __syncthreads();

    const int pr = t & 127, pg = t >> 7;
    const float* s2p = g_s2[head];
    const __half* whT = g_WhT[head];
    const unsigned* mrow = g_mask + row0 + pr;
    const float s1v = sS1[pr], mv = sM[pr];
    float den = 0.f;

    // mma roles: warp grid 4(m) x 2(n); warp tile 32x32
    const int wid = t >> 5, lane = t & 31;
    const int wm = (wid & 3) * 32, wn = (wid >> 2) * 32;
    const int gid = lane >> 2, tig = lane & 3;
    float acc[2][4][4];
    #pragma unroll
    for (int a = 0; a < 2; a++)
        #pragma unroll
        for (int b = 0; b < 4; b++)
            #pragma unroll
            for (int c = 0; c < 4; c++) acc[a][b][c] = 0.f;

    // ldmatrix lane-address byte offsets (within a buffer)
    //  A (16x16 tile at row wm+mt*16, col k0): row = wm + (lane&15), col = k0 + ((lane>>4)<<3)
    const uint32_t aOff = (uint32_t)(((wm + (lane & 15)) * PP + ((lane >> 4) << 3)) * 2);
    //  B (two 8-row n tiles per ldmatrix): row = wn + ((lane>>4)<<3) + (lane&7), col = k0 + (((lane>>3)&1)<<3)
    const uint32_t bOff = (uint32_t)(((wn + ((lane >> 4) << 3) + (lane & 7)) * PP + (((lane >> 3) & 1) << 3)) * 2);
    const uint32_t pBase[2] = { smem_u32(sP[0]), smem_u32(sP[1]) };
    const uint32_t bBase[2] = { smem_u32(sB[0]), smem_u32(sB[1]) };

    // B staging role: n = t>>2 (0..63), kk = (t&3)*8
    const int bn = t >> 2, bk = (t & 3) * 8;
    const __half* bsrc = whT + (size_t)bn * N + bk;

    // prologue
    gen_p_tile(sP[0], pr, pg, mrow[0], s1v, mv, s2p, 0, den);
    *(uint4*)(sB[0] + bn * PP + bk) = *(const uint4*)(bsrc);
    __syncthreads();

    for (int kt = 0; kt < NW; kt++) {
        const int b = kt & 1;
        if (kt + 1 < NW) {
            int j0 = (kt + 1) << 5;
            gen_p_tile(sP[b ^ 1], pr, pg, mrow[(size_t)(kt + 1) * N], s1v, mv, s2p, j0, den);
            *(uint4*)(sB[b ^ 1] + bn * PP + bk) = *(const uint4*)(bsrc + j0);
        }
        // MMA on buffer b via ldmatrix
        const uint32_t pA = pBase[b] + aOff;
        const uint32_t pB2 = bBase[b] + bOff;
        #pragma unroll
        for (int ks = 0; ks < 2; ks++) {
            const uint32_t kOfs = (uint32_t)(ks * 16 * 2);
            uint32_t a[2][4], bb[4][2];
            ldm_x4(a[0], pA + kOfs);
            ldm_x4(a[1], pA + kOfs + 16 * PP * 2);
            uint32_t br[4];
            ldm_x4(br, pB2 + kOfs);                       // n tiles 0,1
            bb[0][0] = br[0]; bb[0][1] = br[1]; bb[1][0] = br[2]; bb[1][1] = br[3];
            ldm_x4(br, pB2 + kOfs + 16 * PP * 2);         // n tiles 2,3
            bb[2][0] = br[0]; bb[2][1] = br[1]; bb[3][0] = br[2]; bb[3][1] = br[3];
            #pragma unroll
            for (int mt = 0; mt < 2; mt++)
                #pragma unroll
                for (int nt = 0; nt < 4; nt++)
                    mma16816(acc[mt][nt], a[mt], bb[nt]);
        }
        __syncthreads();
    }
    sDen[pg][pr] = den;
    __syncthreads();

    // epilogue: normalize + store fp32 to g_h
    #pragma unroll
    for (int mt = 0; mt < 2; mt++) {
        int r1 = wm + mt * 16 + gid;
        int r2 = r1 + 8;
        float inv1 = 1.f / (sDen[0][r1] + sDen[1][r1]);
        float inv2 = 1.f / (sDen[0][r2] + sDen[1][r2]);
        float* d1 = g_h + (size_t)(row0 + r1) * (HEADS * FH) + head * FH;
        float* d2 = g_h + (size_t)(row0 + r2) * (HEADS * FH) + head * FH;
        #pragma unroll
        for (int nt = 0; nt < 4; nt++) {
            int c = wn + nt * 8 + tig * 2;
            *(float2*)(d1 + c) = make_float2(acc[mt][nt][0] * inv1, acc[mt][nt][1] * inv1);
            *(float2*)(d2 + c) = make_float2(acc[mt][nt][2] * inv2, acc[mt][nt][3] * inv2);
        }
    }
}

// ---------------- K5: Who = h @ W_out (stored transposed fp16), s1o/s2o, max ----------------
__global__ void k5_outprep(const float* __restrict__ W_out,
                           const float* __restrict__ a_out) {
    int row0 = blockIdx.x * 64;
    __shared__ float sH[64][133];
    __shared__ float sWo[128][16];
    __shared__ float sA[32];
    __shared__ float sOut[64][17];
    __shared__ float sRed[2];
    int t = threadIdx.x;  // 256

    #pragma unroll
    for (int i = 0; i < 8; i++) {
        int q = t + 256 * i;
        int r = q >> 5, c = (q & 31) * 4;
        float4 v = *(const float4*)&g_h[(size_t)(row0 + r) * 128 + c];
        sH[r][c] = v.x; sH[r][c + 1] = v.y; sH[r][c + 2] = v.z; sH[r][c + 3] = v.w;
    }
    #pragma unroll
    for (int i = 0; i < 2; i++) {
        int q = t + 256 * i;
        int k = q >> 2, c = (q & 3) * 4;
        *(float4*)&sWo[k][c] = *(const float4*)&W_out[k * 16 + c];
    }
    if (t < 32) sA[t] = a_out[t];
    __syncthreads();

    int r = t & 63, cg = t >> 6;
    float4 a4 = make_float4(0.f, 0.f, 0.f, 0.f);
    for (int k = 0; k < 128; k++) {
        float hv = sH[r][k];
        float4 w4 = *(float4*)&sWo[k][cg * 4];
        a4.x += hv * w4.x; a4.y += hv * w4.y; a4.z += hv * w4.z; a4.w += hv * w4.w;
    }
    sOut[r][cg * 4 + 0] = a4.x; sOut[r][cg * 4 + 1] = a4.y;
    sOut[r][cg * 4 + 2] = a4.z; sOut[r][cg * 4 + 3] = a4.w;
    __syncthreads();

    if (t < 64) {
        int row = row0 + t;
        float s1 = 0.f, s2 = 0.f;
        #pragma unroll
        for (int c = 0; c < COUT; c++) {
            float v = sOut[t][c];
            s1 += v * sA[c];
            s2 += v * sA[COUT + c];
            g_WhoT[(size_t)c * N + row] = __float2half(v);
        }
        g_s1o[row] = s1;
        g_s2o[row] = s2;
        float m = s2;
        #pragma unroll
        for (int off = 16; off > 0; off >>= 1)
            m = fmaxf(m, __shfl_down_sync(0xFFFFFFFFu, m, off));
        if ((t & 31) == 0) sRed[t >> 5] = m;
    }
    __syncthreads();
    if (t == 0) atomicMaxF(&g_s2omax, fmaxf(sRed[0], sRed[1]));
}

// ---------------- K6: out-layer attention (mma.sync + ldmatrix) + elu + log_softmax ----------------
// BM=128, BN=16, BK=32, 256 threads, grid 64.
__global__ void __launch_bounds__(256) k6_attn_tc(float* __restrict__ out) {
    const int row0 = blockIdx.x * 128;
    __shared__ __align__(16) __half sP[2][128 * PP];
    __shared__ __align__(16) __half sB[2][16 * PP];
    __shared__ float sS1[128], sM[128], sDen[2][128];
    __shared__ float sO[128][18];

    const int t = threadIdx.x;
    if (t < 128) {
        float v = g_s1o[row0 + t];
        sS1[t] = v;
        float e = v + g_s2omax;
        sM[t] = e > 0.f ? e : ALPHA * e;
    }
    __syncthreads();

    const int pr = t & 127, pg = t >> 7;
    const unsigned* mrow = g_mask + row0 + pr;
    const float s1v = sS1[pr], mv = sM[pr];
    float den = 0.f;

    const int wid = t >> 5, lane = t & 31;
    const int wm = wid * 16;                  // warp rows
    const int gid = lane >> 2, tig = lane & 3;
    float acc[2][4];
    #pragma unroll
    for (int a = 0; a < 2; a++)
        #pragma unroll
        for (int c = 0; c < 4; c++) acc[a][c] = 0.f;

    const uint32_t aOff = (uint32_t)(((wm + (lane & 15)) * PP + ((lane >> 4) << 3)) * 2);
    // B: row = ((lane>>4)<<3) + (lane&7), col = k0 + (((lane>>3)&1)<<3)
    const uint32_t bOff = (uint32_t)(((((lane >> 4) << 3) + (lane & 7)) * PP + (((lane >> 3) & 1) << 3)) * 2);
    const uint32_t pBase[2] = { smem_u32(sP[0]), smem_u32(sP[1]) };
    const uint32_t bBase[2] = { smem_u32(sB[0]), smem_u32(sB[1]) };

    const int bn = t >> 2, bk = (t & 3) * 8;   // t<64 stages B (16 rows)
    const __half* bsrc = g_WhoT + (size_t)bn * N + bk;

    gen_p_tile(sP[0], pr, pg, mrow[0], s1v, mv, g_s2o, 0, den);
    if (t < 64) *(uint4*)(sB[0] + bn * PP + bk) = *(const uint4*)(bsrc);
    __syncthreads();

    for (int kt = 0; kt < NW; kt++) {
        const int b = kt & 1;
        if (kt + 1 < NW) {
            int j0 = (kt + 1) << 5;
            gen_p_tile(sP[b ^ 1], pr, pg, mrow[(size_t)(kt + 1) * N], s1v, mv, g_s2o, j0, den);
            if (t < 64) *(uint4*)(sB[b ^ 1] + bn * PP + bk) = *(const uint4*)(bsrc + j0);
        }
        const uint32_t pA = pBase[b] + aOff;
        const uint32_t pB2 = bBase[b] + bOff;
        #pragma unroll
        for (int ks = 0; ks < 2; ks++) {
            const uint32_t kOfs = (uint32_t)(ks * 16 * 2);
            uint32_t a[4], br[4];
            ldm_x4(a, pA + kOfs);
            ldm_x4(br, pB2 + kOfs);     // r0=nt0 klo, r1=nt0 khi, r2=nt1 klo, r3=nt1 khi
            uint32_t bb0[2] = { br[0], br[1] };
            uint32_t bb1[2] = { br[2], br[3] };
            mma16816(acc[0], a, bb0);
            mma16816(acc[1], a, bb1);
        }
        __syncthreads();
    }
    sDen[pg][pr] = den;
    __syncthreads();

    {   // normalized h -> sO
        int r1 = wm + gid, r2 = r1 + 8;
        float inv1 = 1.f / (sDen[0][r1] + sDen[1][r1]);
        float inv2 = 1.f / (sDen[0][r2] + sDen[1][r2]);
        #pragma unroll
        for (int nt = 0; nt < 2; nt++) {
            int c = nt * 8 + tig * 2;
            sO[r1][c]     = acc[nt][0] * inv1;
            sO[r1][c + 1] = acc[nt][1] * inv1;
            sO[r2][c]     = acc[nt][2] * inv2;
            sO[r2][c + 1] = acc[nt][3] * inv2;
        }
    }
    __syncthreads();

    if (t < 128) {
        float v[COUT];
        float m = -INFINITY;
        #pragma unroll
        for (int c = 0; c < COUT; c++) {
            float xv = sO[t][c];
            xv = xv > 0.f ? xv : (__expf(xv) - 1.f);   // elu
            v[c] = xv;
            m = fmaxf(m, xv);
        }
        float s = 0.f;
        #pragma unroll
        for (int c = 0; c < COUT; c++) s += __expf(v[c] - m);
        float lse = m + logf(s);
        float* dst = out + (size_t)(row0 + t) * COUT;
        #pragma unroll
        for (int c = 0; c < COUT; c += 4)
            *(float4*)(dst + c) = make_float4(v[c] - lse, v[c + 1] - lse,
                                              v[c + 2] - lse, v[c + 3] - lse);
    }
}

// ---------------- launch ----------------
extern "C" void kernel_launch(void* const* d_in, const int* in_sizes, int n_in,
                              void* d_out, int out_size) {
    const float* x       = (const float*)d_in[0];
    const int*   adj     = (const int*)d_in[1];
    const float* W_heads = (const float*)d_in[2];
    const float* a_heads = (const float*)d_in[3];
    const float* W_out   = (const float*)d_in[4];
    const float* a_out   = (const float*)d_in[5];
    float* out = (float*)d_out;

    k0_init<<<1, 1>>>();
    k1_pack<<<1024, 256>>>(adj);
    k2_wh<<<dim3(128, 2), 256>>>(x, W_heads, a_heads);
    k4_attn_tc<<<dim3(64, 2), 256>>>();
    k5_outprep<<<128, 256>>>(W_out, a_out);
    k6_attn_tc<<<64, 256>>>(out);
}

// round 7
// speedup vs baseline: 1.0498x; 1.0498x over previous
#include <cuda_runtime.h>
#include <cuda_fp16.h>
#include <math.h>
#include <cstdint>

#define N      8192
#define FH     64
#define HEADS  2
#define COUT   16
#define FIN    64
#define NW     256       // mask words per row
#define ALPHA  0.2f
#define PP     40        // smem pitch in halfs (80B: 16B-aligned, conflict-free frags+ldmatrix)

// ---------------- scratch ----------------
__device__ __align__(16) unsigned g_mask[NW * N];          // g_mask[w*N + i], bit b <-> col w*32+b
__device__ __align__(16) __half   g_WhT[HEADS][FH * N];    // transposed Wh (fp16): [f][row]
__device__ __align__(16) float    g_s1[HEADS][N];
__device__ __align__(16) float    g_s2[HEADS][N];
__device__               float    g_s2max[HEADS];
__device__ __align__(16) float    g_h[(size_t)N * (HEADS * FH)];  // [N][128] fp32
__device__ __align__(16) __half   g_WhoT[COUT * N];        // transposed Who (fp16): [c][row]
__device__ __align__(16) float    g_s1o[N];
__device__ __align__(16) float    g_s2o[N];
__device__               float    g_s2omax;

__device__ __forceinline__ uint32_t smem_u32(const void* p) {
    return (uint32_t)__cvta_generic_to_shared(p);
}

__device__ __forceinline__ void mma16816(float* c, const uint32_t* a, const uint32_t* b) {
    asm volatile("mma.sync.aligned.m16n8k16.row.col.f32.f16.f16.f32 "
        "{%0,%1,%2,%3}, {%4,%5,%6,%7}, {%8,%9}, {%0,%1,%2,%3};"
        : "+f"(c[0]), "+f"(c[1]), "+f"(c[2]), "+f"(c[3])
        : "r"(a[0]), "r"(a[1]), "r"(a[2]), "r"(a[3]), "r"(b[0]), "r"(b[1]));
}

__device__ __forceinline__ void ldm_x4(uint32_t* r, uint32_t addr) {
    asm volatile("ldmatrix.sync.aligned.m8n8.x4.shared.b16 {%0,%1,%2,%3}, [%4];"
        : "=r"(r[0]), "=r"(r[1]), "=r"(r[2]), "=r"(r[3]) : "r"(addr));
}

__device__ __forceinline__ float atomicMaxF(float* addr, float v) {
    int* ia = (int*)addr;
    int old = *ia;
    while (__int_as_float(old) < v) {
        int assumed = old;
        old = atomicCAS(ia, assumed, __float_as_int(v));
        if (old == assumed) break;
    }
    return __int_as_float(old);
}

__global__ void k0_init() {
    g_s2max[0] = -INFINITY;
    g_s2max[1] = -INFINITY;
    g_s2omax   = -INFINITY;
}

// ---------------- K1: pack adjacency into transposed bitmask (MLP=8) ----------------
__global__ void k1_pack(const int* __restrict__ adj) {
    int warp = (blockIdx.x * blockDim.x + threadIdx.x) >> 5;
    int lane = threadIdx.x & 31;
    if (warp >= N) return;
    const int* arow = adj + (size_t)warp * N;
    for (int w = 0; w < NW; w += 8) {
        int v[8];
        #pragma unroll
        for (int i = 0; i < 8; i++) v[i] = arow[(w + i) * 32 + lane];
        unsigned b[8];
        #pragma unroll
        for (int i = 0; i < 8; i++) b[i] = __ballot_sync(0xFFFFFFFFu, v[i] > 0);
        if (lane == 0) {
            #pragma unroll
            for (int i = 0; i < 8; i++) g_mask[(size_t)(w + i) * N + warp] = b[i];
        }
    }
}

// ---------------- K2: Wh = x @ W per head (stored transposed fp16), s1/s2, max(s2) ----------------
__global__ void k2_wh(const float* __restrict__ x,
                      const float* __restrict__ W_heads,
                      const float* __restrict__ a_heads) {
    int head = blockIdx.y;
    int row0 = blockIdx.x * 64;
    __shared__ float sX[64][65];
    __shared__ float sW[64][64];
    __shared__ float sA[2 * FH];
    __shared__ float sRed[2];
    int t = threadIdx.x;  // 256

    #pragma unroll
    for (int i = 0; i < 4; i++) {
        int q = t + 256 * i;
        int r = q >> 4, c = (q & 15) * 4;
        float4 v = *(const float4*)&x[(size_t)(row0 + r) * FIN + c];
        sX[r][c] = v.x; sX[r][c + 1] = v.y; sX[r][c + 2] = v.z; sX[r][c + 3] = v.w;
    }
    const float* W = W_heads + head * FIN * FH;
    #pragma unroll
    for (int i = 0; i < 4; i++) {
        int q = t + 256 * i;
        int r = q >> 4, c = (q & 15) * 4;
        *(float4*)&sW[r][c] = *(const float4*)&W[r * FH + c];
    }
    if (t < 2 * FH) sA[t] = a_heads[head * 2 * FH + t];
    __syncthreads();

    int r = t & 63, cg = t >> 6;
    float4 acc[4];
    #pragma unroll
    for (int j = 0; j < 4; j++) acc[j] = make_float4(0.f, 0.f, 0.f, 0.f);
    for (int k = 0; k < FIN; k++) {
        float xv = sX[r][k];
        #pragma unroll
        for (int j = 0; j < 4; j++) {
            float4 w4 = *(float4*)&sW[k][cg * 16 + j * 4];
            acc[j].x += xv * w4.x; acc[j].y += xv * w4.y;
            acc[j].z += xv * w4.z; acc[j].w += xv * w4.w;
        }
    }
    __syncthreads();
    #pragma unroll
    for (int j = 0; j < 4; j++) {
        sX[r][cg * 16 + j * 4 + 0] = acc[j].x;
        sX[r][cg * 16 + j * 4 + 1] = acc[j].y;
        sX[r][cg * 16 + j * 4 + 2] = acc[j].z;
        sX[r][cg * 16 + j * 4 + 3] = acc[j].w;
    }
    __syncthreads();

    if (t < 64) {
        int row = row0 + t;
        float s1 = 0.f, s2 = 0.f;
        float* o = sX[t];
        #pragma unroll
        for (int f = 0; f < FH; f++) {
            s1 += o[f] * sA[f];
            s2 += o[f] * sA[FH + f];
            g_WhT[head][(size_t)f * N + row] = __float2half(o[f]);
        }
        g_s1[head][row] = s1;
        g_s2[head][row] = s2;
        float m = s2;
        #pragma unroll
        for (int off = 16; off > 0; off >>= 1)
            m = fmaxf(m, __shfl_down_sync(0xFFFFFFFFu, m, off));
        if ((t & 31) == 0) sRed[t >> 5] = m;
    }
    __syncthreads();
    if (t == 0) atomicMaxF(&g_s2max[head], fmaxf(sRed[0], sRed[1]));
}

// ---------------- P-tile generation from prefetched registers ----------------
__device__ __forceinline__ void gen_p_regs(__half* sPb, int pr, int pg,
                                           unsigned mw, float s1v, float mv,
                                           const float4* s2v, float& den) {
    const int kbase = pg << 4;
    const float* s2f = (const float*)s2v;
    uint32_t packed[8];
    #pragma unroll
    for (int i = 0; i < 8; i++) {
        int k = kbase + 2 * i;
        float e0 = s1v + s2f[2 * i];
        e0 = e0 > 0.f ? e0 : ALPHA * e0;
        float p0 = ((mw >> k) & 1u) ? __expf(e0 - mv) : 0.f;
        float e1 = s1v + s2f[2 * i + 1];
        e1 = e1 > 0.f ? e1 : ALPHA * e1;
        float p1 = ((mw >> (k + 1)) & 1u) ? __expf(e1 - mv) : 0.f;
        den += p0 + p1;
        __half2 h = __floats2half2_rn(p0, p1);
        packed[i] = *(uint32_t*)&h;
    }
    uint4* dst = (uint4*)(sPb + pr * PP + kbase);
    dst[0] = make_uint4(packed[0], packed[1], packed[2], packed[3]);
    dst[1] = make_uint4(packed[4], packed[5], packed[6], packed[7]);
}

// ---------------- K4: fused masked-softmax attention GEMM (prefetched, mma.sync) ----------------
// BM=128, BN=64, BK=32, 256 threads. grid (64,2) = 128 blocks (single wave).
// Tile kt uses prefetch slot kt&1; loads for kt+2 issued at top of iteration kt.
__global__ void __launch_bounds__(256) k4_attn_tc() {
    const int head = blockIdx.y;
    const int row0 = blockIdx.x * 128;
    __shared__ __align__(16) __half sP[2][128 * PP];   // 2 x 10 KB
    __shared__ __align__(16) __half sB[2][64 * PP];    // 2 x 5 KB
    __shared__ float sS1[128], sM[128], sDen[2][128];

    const int t = threadIdx.x;
    if (t < 128) {
        float v = g_s1[head][row0 + t];
        sS1[t] = v;
        float e = v + g_s2max[head];            // lrelu monotone -> valid stabilizer
        sM[t] = e > 0.f ? e : ALPHA * e;
    }
    __syncthreads();

    const int pr = t & 127, pg = t >> 7;
    const float* s2p = g_s2[head] + (pg << 4);
    const __half* whT = g_WhT[head];
    const unsigned* mrow = g_mask + row0 + pr;
    const float s1v = sS1[pr], mv = sM[pr];
    float den = 0.f;

    const int wid = t >> 5, lane = t & 31;
    const int wm = (wid & 3) * 32, wn = (wid >> 2) * 32;
    const int gid = lane >> 2, tig = lane & 3;
    float acc[2][4][4];
    #pragma unroll
    for (int a = 0; a < 2; a++)
        #pragma unroll
        for (int b = 0; b < 4; b++)
            #pragma unroll
            for (int c = 0; c < 4; c++) acc[a][b][c] = 0.f;

    const uint32_t aOff = (uint32_t)(((wm + (lane & 15)) * PP + ((lane >> 4) << 3)) * 2);
    const uint32_t bOff = (uint32_t)(((wn + ((lane >> 4) << 3) + (lane & 7)) * PP + (((lane >> 3) & 1) << 3)) * 2);
    const uint32_t pBase[2] = { smem_u32(sP[0]), smem_u32(sP[1]) };
    const uint32_t bBase[2] = { smem_u32(sB[0]), smem_u32(sB[1]) };

    const int bn = t >> 2, bk = (t & 3) * 8;
    const __half* bsrc = whT + (size_t)bn * N + bk;

    // prefetch slots: tile kt -> slot kt&1
    unsigned mwR[2];
    float4   s2R[2][4];
    uint4    bR[2];
    #pragma unroll
    for (int s = 0; s < 2; s++) {
        mwR[s] = mrow[(size_t)s * N];
        #pragma unroll
        for (int q = 0; q < 4; q++) s2R[s][q] = *(const float4*)(s2p + (s << 5) + 4 * q);
        bR[s] = *(const uint4*)(bsrc + (s << 5));
    }
    // prologue: gen tile 0 from slot 0
    gen_p_regs(sP[0], pr, pg, mwR[0], s1v, mv, s2R[0], den);
    *(uint4*)(sB[0] + bn * PP + bk) = bR[0];
    __syncthreads();

    for (int kt = 0; kt < NW; kt++) {
        const int b = kt & 1;
        // issue loads for kt+2 into slot b (tile kt's data already consumed)
        if (kt + 2 < NW) {
            const int j2 = (kt + 2) << 5;
            mwR[b] = mrow[(size_t)(kt + 2) * N];
            #pragma unroll
            for (int q = 0; q < 4; q++) s2R[b][q] = *(const float4*)(s2p + j2 + 4 * q);
            bR[b] = *(const uint4*)(bsrc + j2);
        }
        // gen tile kt+1 from slot b^1 into buffers b^1
        if (kt + 1 < NW) {
            gen_p_regs(sP[b ^ 1], pr, pg, mwR[b ^ 1], s1v, mv, s2R[b ^ 1], den);
            *(uint4*)(sB[b ^ 1] + bn * PP + bk) = bR[b ^ 1];
        }
        // MMA on buffers b
        const uint32_t pA = pBase[b] + aOff;
        const uint32_t pB2 = bBase[b] + bOff;
        #pragma unroll
        for (int ks = 0; ks < 2; ks++) {
            const uint32_t kOfs = (uint32_t)(ks * 16 * 2);
            uint32_t a[2][4], bb[4][2];
            ldm_x4(a[0], pA + kOfs);
            ldm_x4(a[1], pA + kOfs + 16 * PP * 2);
            uint32_t br[4];
            ldm_x4(br, pB2 + kOfs);
            bb[0][0] = br[0]; bb[0][1] = br[1]; bb[1][0] = br[2]; bb[1][1] = br[3];
            ldm_x4(br, pB2 + kOfs + 16 * PP * 2);
            bb[2][0] = br[0]; bb[2][1] = br[1]; bb[3][0] = br[2]; bb[3][1] = br[3];
            #pragma unroll
            for (int mt = 0; mt < 2; mt++)
                #pragma unroll
                for (int nt = 0; nt < 4; nt++)
                    mma16816(acc[mt][nt], a[mt], bb[nt]);
        }
        __syncthreads();
    }
    sDen[pg][pr] = den;
    __syncthreads();

    #pragma unroll
    for (int mt = 0; mt < 2; mt++) {
        int r1 = wm + mt * 16 + gid;
        int r2 = r1 + 8;
        float inv1 = 1.f / (sDen[0][r1] + sDen[1][r1]);
        float inv2 = 1.f / (sDen[0][r2] + sDen[1][r2]);
        float* d1 = g_h + (size_t)(row0 + r1) * (HEADS * FH) + head * FH;
        float* d2 = g_h + (size_t)(row0 + r2) * (HEADS * FH) + head * FH;
        #pragma unroll
        for (int nt = 0; nt < 4; nt++) {
            int c = wn + nt * 8 + tig * 2;
            *(float2*)(d1 + c) = make_float2(acc[mt][nt][0] * inv1, acc[mt][nt][1] * inv1);
            *(float2*)(d2 + c) = make_float2(acc[mt][nt][2] * inv2, acc[mt][nt][3] * inv2);
        }
    }
}

// ---------------- K5: Who = h @ W_out (stored transposed fp16), s1o/s2o, max ----------------
__global__ void k5_outprep(const float* __restrict__ W_out,
                           const float* __restrict__ a_out) {
    int row0 = blockIdx.x * 64;
    __shared__ float sH[64][133];
    __shared__ float sWo[128][16];
    __shared__ float sA[32];
    __shared__ float sOut[64][17];
    __shared__ float sRed[2];
    int t = threadIdx.x;  // 256

    #pragma unroll
    for (int i = 0; i < 8; i++) {
        int q = t + 256 * i;
        int r = q >> 5, c = (q & 31) * 4;
        float4 v = *(const float4*)&g_h[(size_t)(row0 + r) * 128 + c];
        sH[r][c] = v.x; sH[r][c + 1] = v.y; sH[r][c + 2] = v.z; sH[r][c + 3] = v.w;
    }
    #pragma unroll
    for (int i = 0; i < 2; i++) {
        int q = t + 256 * i;
        int k = q >> 2, c = (q & 3) * 4;
        *(float4*)&sWo[k][c] = *(const float4*)&W_out[k * 16 + c];
    }
    if (t < 32) sA[t] = a_out[t];
    __syncthreads();

    int r = t & 63, cg = t >> 6;
    float4 a4 = make_float4(0.f, 0.f, 0.f, 0.f);
    for (int k = 0; k < 128; k++) {
        float hv = sH[r][k];
        float4 w4 = *(float4*)&sWo[k][cg * 4];
        a4.x += hv * w4.x; a4.y += hv * w4.y; a4.z += hv * w4.z; a4.w += hv * w4.w;
    }
    sOut[r][cg * 4 + 0] = a4.x; sOut[r][cg * 4 + 1] = a4.y;
    sOut[r][cg * 4 + 2] = a4.z; sOut[r][cg * 4 + 3] = a4.w;
    __syncthreads();

    if (t < 64) {
        int row = row0 + t;
        float s1 = 0.f, s2 = 0.f;
        #pragma unroll
        for (int c = 0; c < COUT; c++) {
            float v = sOut[t][c];
            s1 += v * sA[c];
            s2 += v * sA[COUT + c];
            g_WhoT[(size_t)c * N + row] = __float2half(v);
        }
        g_s1o[row] = s1;
        g_s2o[row] = s2;
        float m = s2;
        #pragma unroll
        for (int off = 16; off > 0; off >>= 1)
            m = fmaxf(m, __shfl_down_sync(0xFFFFFFFFu, m, off));
        if ((t & 31) == 0) sRed[t >> 5] = m;
    }
    __syncthreads();
    if (t == 0) atomicMaxF(&g_s2omax, fmaxf(sRed[0], sRed[1]));
}

// ---------------- K6: out-layer attention (prefetched, mma.sync) + elu + log_softmax ----------------
__global__ void __launch_bounds__(256) k6_attn_tc(float* __restrict__ out) {
    const int row0 = blockIdx.x * 128;
    __shared__ __align__(16) __half sP[2][128 * PP];
    __shared__ __align__(16) __half sB[2][16 * PP];
    __shared__ float sS1[128], sM[128], sDen[2][128];
    __shared__ float sO[128][18];

    const int t = threadIdx.x;
    if (t < 128) {
        float v = g_s1o[row0 + t];
        sS1[t] = v;
        float e = v + g_s2omax;
        sM[t] = e > 0.f ? e : ALPHA * e;
    }
    __syncthreads();

    const int pr = t & 127, pg = t >> 7;
    const float* s2p = g_s2o + (pg << 4);
    const unsigned* mrow = g_mask + row0 + pr;
    const float s1v = sS1[pr], mv = sM[pr];
    float den = 0.f;

    const int wid = t >> 5, lane = t & 31;
    const int wm = wid * 16;
    const int gid = lane >> 2, tig = lane & 3;
    float acc[2][4];
    #pragma unroll
    for (int a = 0; a < 2; a++)
        #pragma unroll
        for (int c = 0; c < 4; c++) acc[a][c] = 0.f;

    const uint32_t aOff = (uint32_t)(((wm + (lane & 15)) * PP + ((lane >> 4) << 3)) * 2);
    const uint32_t bOff = (uint32_t)(((((lane >> 4) << 3) + (lane & 7)) * PP + (((lane >> 3) & 1) << 3)) * 2);
    const uint32_t pBase[2] = { smem_u32(sP[0]), smem_u32(sP[1]) };
    const uint32_t bBase[2] = { smem_u32(sB[0]), smem_u32(sB[1]) };

    const int bn = t >> 2, bk = (t & 3) * 8;
    const __half* bsrc = g_WhoT + (size_t)bn * N + bk;
    const bool bstage = (t < 64);

    unsigned mwR[2];
    float4   s2R[2][4];
    uint4    bR[2];
    #pragma unroll
    for (int s = 0; s < 2; s++) {
        mwR[s] = mrow[(size_t)s * N];
        #pragma unroll
        for (int q = 0; q < 4; q++) s2R[s][q] = *(const float4*)(s2p + (s << 5) + 4 * q);
        if (bstage) bR[s] = *(const uint4*)(bsrc + (s << 5));
    }
    gen_p_regs(sP[0], pr, pg, mwR[0], s1v, mv, s2R[0], den);
    if (bstage) *(uint4*)(sB[0] + bn * PP + bk) = bR[0];
    __syncthreads();

    for (int kt = 0; kt < NW; kt++) {
        const int b = kt & 1;
        if (kt + 2 < NW) {
            const int j2 = (kt + 2) << 5;
            mwR[b] = mrow[(size_t)(kt + 2) * N];
            #pragma unroll
            for (int q = 0; q < 4; q++) s2R[b][q] = *(const float4*)(s2p + j2 + 4 * q);
            if (bstage) bR[b] = *(const uint4*)(bsrc + j2);
        }
        if (kt + 1 < NW) {
            gen_p_regs(sP[b ^ 1], pr, pg, mwR[b ^ 1], s1v, mv, s2R[b ^ 1], den);
            if (bstage) *(uint4*)(sB[b ^ 1] + bn * PP + bk) = bR[b ^ 1];
        }
        const uint32_t pA = pBase[b] + aOff;
        const uint32_t pB2 = bBase[b] + bOff;
        #pragma unroll
        for (int ks = 0; ks < 2; ks++) {
            const uint32_t kOfs = (uint32_t)(ks * 16 * 2);
            uint32_t a[4], br[4];
            ldm_x4(a, pA + kOfs);
            ldm_x4(br, pB2 + kOfs);
            uint32_t bb0[2] = { br[0], br[1] };
            uint32_t bb1[2] = { br[2], br[3] };
            mma16816(acc[0], a, bb0);
            mma16816(acc[1], a, bb1);
        }
        __syncthreads();
    }
    sDen[pg][pr] = den;
    __syncthreads();

    {
        int r1 = wm + gid, r2 = r1 + 8;
        float inv1 = 1.f / (sDen[0][r1] + sDen[1][r1]);
        float inv2 = 1.f / (sDen[0][r2] + sDen[1][r2]);
        #pragma unroll
        for (int nt = 0; nt < 2; nt++) {
            int c = nt * 8 + tig * 2;
            sO[r1][c]     = acc[nt][0] * inv1;
            sO[r1][c + 1] = acc[nt][1] * inv1;
            sO[r2][c]     = acc[nt][2] * inv2;
            sO[r2][c + 1] = acc[nt][3] * inv2;
        }
    }
    __syncthreads();

    if (t < 128) {
        float v[COUT];
        float m = -INFINITY;
        #pragma unroll
        for (int c = 0; c < COUT; c++) {
            float xv = sO[t][c];
            xv = xv > 0.f ? xv : (__expf(xv) - 1.f);   // elu
            v[c] = xv;
            m = fmaxf(m, xv);
        }
        float s = 0.f;
        #pragma unroll
        for (int c = 0; c < COUT; c++) s += __expf(v[c] - m);
        float lse = m + logf(s);
        float* dst = out + (size_t)(row0 + t) * COUT;
        #pragma unroll
        for (int c = 0; c < COUT; c += 4)
            *(float4*)(dst + c) = make_float4(v[c] - lse, v[c + 1] - lse,
                                              v[c + 2] - lse, v[c + 3] - lse);
    }
}

// ---------------- launch ----------------
extern "C" void kernel_launch(void* const* d_in, const int* in_sizes, int n_in,
                              void* d_out, int out_size) {
    const float* x       = (const float*)d_in[0];
    const int*   adj     = (const int*)d_in[1];
    const float* W_heads = (const float*)d_in[2];
    const float* a_heads = (const float*)d_in[3];
    const float* W_out   = (const float*)d_in[4];
    const float* a_out   = (const float*)d_in[5];
    float* out = (float*)d_out;

    k0_init<<<1, 1>>>();
    k1_pack<<<1024, 256>>>(adj);
    k2_wh<<<dim3(128, 2), 256>>>(x, W_heads, a_heads);
    k4_attn_tc<<<dim3(64, 2), 256>>>();
    k5_outprep<<<128, 256>>>(W_out, a_out);
    k6_attn_tc<<<64, 256>>>(out);
}

// round 8
// speedup vs baseline: 1.2400x; 1.1811x over previous
#include <cuda_runtime.h>
#include <cuda_fp16.h>
#include <math.h>
#include <cstdint>

#define N      8192
#define FH     64
#define HEADS  2
#define COUT   16
#define FIN    64
#define NW     256       // mask words per row
#define ALPHA  0.2f
#define PP     40        // smem pitch in halfs (80B: 16B-aligned, conflict-free frags+ldmatrix)

// ---------------- scratch ----------------
__device__ __align__(16) unsigned g_mask[NW * N];          // g_mask[w*N + i], bit b <-> col w*32+b
__device__ __align__(16) __half   g_WhT[HEADS][FH * N];    // transposed Wh (fp16): [f][row]
__device__ __align__(16) float    g_s1[HEADS][N];
__device__ __align__(16) float    g_s2[HEADS][N];
__device__               float    g_s2max[HEADS];
__device__ __align__(16) float    g_h[(size_t)N * (HEADS * FH)];  // [N][128] fp32
__device__ __align__(16) __half   g_WhoT[COUT * N];        // transposed Who (fp16): [c][row]
__device__ __align__(16) float    g_s1o[N];
__device__ __align__(16) float    g_s2o[N];
__device__               float    g_s2omax;

__device__ __forceinline__ uint32_t smem_u32(const void* p) {
    return (uint32_t)__cvta_generic_to_shared(p);
}

__device__ __forceinline__ void mma16816(float* c, const uint32_t* a, const uint32_t* b) {
    asm volatile("mma.sync.aligned.m16n8k16.row.col.f32.f16.f16.f32 "
        "{%0,%1,%2,%3}, {%4,%5,%6,%7}, {%8,%9}, {%0,%1,%2,%3};"
        : "+f"(c[0]), "+f"(c[1]), "+f"(c[2]), "+f"(c[3])
        : "r"(a[0]), "r"(a[1]), "r"(a[2]), "r"(a[3]), "r"(b[0]), "r"(b[1]));
}

__device__ __forceinline__ void ldm_x4(uint32_t* r, uint32_t addr) {
    asm volatile("ldmatrix.sync.aligned.m8n8.x4.shared.b16 {%0,%1,%2,%3}, [%4];"
        : "=r"(r[0]), "=r"(r[1]), "=r"(r[2]), "=r"(r[3]) : "r"(addr));
}

__device__ __forceinline__ void ldm_x2(uint32_t* r, uint32_t addr) {
    asm volatile("ldmatrix.sync.aligned.m8n8.x2.shared.b16 {%0,%1}, [%2];"
        : "=r"(r[0]), "=r"(r[1]) : "r"(addr));
}

__device__ __forceinline__ float atomicMaxF(float* addr, float v) {
    int* ia = (int*)addr;
    int old = *ia;
    while (__int_as_float(old) < v) {
        int assumed = old;
        old = atomicCAS(ia, assumed, __float_as_int(v));
        if (old == assumed) break;
    }
    return __int_as_float(old);
}

__global__ void k0_init() {
    g_s2max[0] = -INFINITY;
    g_s2max[1] = -INFINITY;
    g_s2omax   = -INFINITY;
}

// ---------------- K1: pack adjacency into transposed bitmask (MLP=8) ----------------
__global__ void k1_pack(const int* __restrict__ adj) {
    int warp = (blockIdx.x * blockDim.x + threadIdx.x) >> 5;
    int lane = threadIdx.x & 31;
    if (warp >= N) return;
    const int* arow = adj + (size_t)warp * N;
    for (int w = 0; w < NW; w += 8) {
        int v[8];
        #pragma unroll
        for (int i = 0; i < 8; i++) v[i] = arow[(w + i) * 32 + lane];
        unsigned b[8];
        #pragma unroll
        for (int i = 0; i < 8; i++) b[i] = __ballot_sync(0xFFFFFFFFu, v[i] > 0);
        if (lane == 0) {
            #pragma unroll
            for (int i = 0; i < 8; i++) g_mask[(size_t)(w + i) * N + warp] = b[i];
        }
    }
}

// ---------------- K2: Wh = x @ W per head (stored transposed fp16), s1/s2, max(s2) ----------------
__global__ void k2_wh(const float* __restrict__ x,
                      const float* __restrict__ W_heads,
                      const float* __restrict__ a_heads) {
    int head = blockIdx.y;
    int row0 = blockIdx.x * 64;
    __shared__ float sX[64][65];
    __shared__ float sW[64][64];
    __shared__ float sA[2 * FH];
    __shared__ float sRed[2];
    int t = threadIdx.x;  // 256

    #pragma unroll
    for (int i = 0; i < 4; i++) {
        int q = t + 256 * i;
        int r = q >> 4, c = (q & 15) * 4;
        float4 v = *(const float4*)&x[(size_t)(row0 + r) * FIN + c];
        sX[r][c] = v.x; sX[r][c + 1] = v.y; sX[r][c + 2] = v.z; sX[r][c + 3] = v.w;
    }
    const float* W = W_heads + head * FIN * FH;
    #pragma unroll
    for (int i = 0; i < 4; i++) {
        int q = t + 256 * i;
        int r = q >> 4, c = (q & 15) * 4;
        *(float4*)&sW[r][c] = *(const float4*)&W[r * FH + c];
    }
    if (t < 2 * FH) sA[t] = a_heads[head * 2 * FH + t];
    __syncthreads();

    int r = t & 63, cg = t >> 6;
    float4 acc[4];
    #pragma unroll
    for (int j = 0; j < 4; j++) acc[j] = make_float4(0.f, 0.f, 0.f, 0.f);
    for (int k = 0; k < FIN; k++) {
        float xv = sX[r][k];
        #pragma unroll
        for (int j = 0; j < 4; j++) {
            float4 w4 = *(float4*)&sW[k][cg * 16 + j * 4];
            acc[j].x += xv * w4.x; acc[j].y += xv * w4.y;
            acc[j].z += xv * w4.z; acc[j].w += xv * w4.w;
        }
    }
    __syncthreads();
    #pragma unroll
    for (int j = 0; j < 4; j++) {
        sX[r][cg * 16 + j * 4 + 0] = acc[j].x;
        sX[r][cg * 16 + j * 4 + 1] = acc[j].y;
        sX[r][cg * 16 + j * 4 + 2] = acc[j].z;
        sX[r][cg * 16 + j * 4 + 3] = acc[j].w;
    }
    __syncthreads();

    if (t < 64) {
        int row = row0 + t;
        float s1 = 0.f, s2 = 0.f;
        float* o = sX[t];
        #pragma unroll
        for (int f = 0; f < FH; f++) {
            s1 += o[f] * sA[f];
            s2 += o[f] * sA[FH + f];
            g_WhT[head][(size_t)f * N + row] = __float2half(o[f]);
        }
        g_s1[head][row] = s1;
        g_s2[head][row] = s2;
        float m = s2;
        #pragma unroll
        for (int off = 16; off > 0; off >>= 1)
            m = fmaxf(m, __shfl_down_sync(0xFFFFFFFFu, m, off));
        if ((t & 31) == 0) sRed[t >> 5] = m;
    }
    __syncthreads();
    if (t == 0) atomicMaxF(&g_s2max[head], fmaxf(sRed[0], sRed[1]));
}

// ---------------- P-tile generation: 8 cols per thread from prefetched regs ----------------
__device__ __forceinline__ void gen_p8(__half* sPb, int pr, int pg,
                                       unsigned mw, float s1v, float mv,
                                       const float4* s2v, float& den) {
    const int kbase = pg << 3;
    const float* s2f = (const float*)s2v;   // 8 floats
    uint32_t packed[4];
    #pragma unroll
    for (int i = 0; i < 4; i++) {
        int k = kbase + 2 * i;
        float e0 = s1v + s2f[2 * i];
        e0 = e0 > 0.f ? e0 : ALPHA * e0;
        float p0 = ((mw >> k) & 1u) ? __expf(e0 - mv) : 0.f;
        float e1 = s1v + s2f[2 * i + 1];
        e1 = e1 > 0.f ? e1 : ALPHA * e1;
        float p1 = ((mw >> (k + 1)) & 1u) ? __expf(e1 - mv) : 0.f;
        den += p0 + p1;
        __half2 h = __floats2half2_rn(p0, p1);
        packed[i] = *(uint32_t*)&h;
    }
    *(uint4*)(sPb + pr * PP + kbase) = make_uint4(packed[0], packed[1], packed[2], packed[3]);
}

// ---------------- K4: fused attention GEMM. BM=64, BN=64, BK=32, 256 thr, grid (128,2) ----------------
// 256 blocks -> 2 CTAs/SM co-resident (16 warps/SM, independent barrier domains).
__global__ void __launch_bounds__(256) k4_attn_tc() {
    const int head = blockIdx.y;
    const int row0 = blockIdx.x * 64;
    __shared__ __align__(16) __half sP[2][64 * PP];    // 2 x 5 KB
    __shared__ __align__(16) __half sB[2][64 * PP];    // 2 x 5 KB
    __shared__ float sS1[64], sM[64], sDen[4][64];

    const int t = threadIdx.x;
    if (t < 64) {
        float v = g_s1[head][row0 + t];
        sS1[t] = v;
        float e = v + g_s2max[head];            // lrelu monotone -> valid stabilizer
        sM[t] = e > 0.f ? e : ALPHA * e;
    }
    __syncthreads();

    const int pr = t & 63, pg = t >> 6;         // 4 col-groups of 8
    const float* s2p = g_s2[head] + (pg << 3);
    const __half* whT = g_WhT[head];
    const unsigned* mrow = g_mask + row0 + pr;
    const float s1v = sS1[pr], mv = sM[pr];
    float den = 0.f;

    // warps: 2(m) x 4(n); warp tile 32x16
    const int wid = t >> 5, lane = t & 31;
    const int wm = (wid & 1) * 32, wn = (wid >> 1) * 16;
    const int gid = lane >> 2, tig = lane & 3;
    float acc[2][2][4];
    #pragma unroll
    for (int a = 0; a < 2; a++)
        #pragma unroll
        for (int b = 0; b < 2; b++)
            #pragma unroll
            for (int c = 0; c < 4; c++) acc[a][b][c] = 0.f;

    const uint32_t aOff = (uint32_t)(((wm + (lane & 15)) * PP + ((lane >> 4) << 3)) * 2);
    const uint32_t bOff = (uint32_t)(((wn + ((lane >> 4) << 3) + (lane & 7)) * PP + (((lane >> 3) & 1) << 3)) * 2);
    const uint32_t pBase[2] = { smem_u32(sP[0]), smem_u32(sP[1]) };
    const uint32_t bBase[2] = { smem_u32(sB[0]), smem_u32(sB[1]) };

    const int bn = t >> 2, bk = (t & 3) * 8;
    const __half* bsrc = whT + (size_t)bn * N + bk;

    // prefetch slots: tile kt -> slot kt&1
    unsigned mwR[2];
    float4   s2R[2][2];
    uint4    bR[2];
    #pragma unroll
    for (int s = 0; s < 2; s++) {
        mwR[s] = mrow[(size_t)s * N];
        s2R[s][0] = *(const float4*)(s2p + (s << 5));
        s2R[s][1] = *(const float4*)(s2p + (s << 5) + 4);
        bR[s] = *(const uint4*)(bsrc + (s << 5));
    }
    gen_p8(sP[0], pr, pg, mwR[0], s1v, mv, s2R[0], den);
    *(uint4*)(sB[0] + bn * PP + bk) = bR[0];
    __syncthreads();

    for (int kt = 0; kt < NW; kt++) {
        const int b = kt & 1;
        if (kt + 2 < NW) {
            const int j2 = (kt + 2) << 5;
            mwR[b] = mrow[(size_t)(kt + 2) * N];
            s2R[b][0] = *(const float4*)(s2p + j2);
            s2R[b][1] = *(const float4*)(s2p + j2 + 4);
            bR[b] = *(const uint4*)(bsrc + j2);
        }
        if (kt + 1 < NW) {
            gen_p8(sP[b ^ 1], pr, pg, mwR[b ^ 1], s1v, mv, s2R[b ^ 1], den);
            *(uint4*)(sB[b ^ 1] + bn * PP + bk) = bR[b ^ 1];
        }
        const uint32_t pA = pBase[b] + aOff;
        const uint32_t pB2 = bBase[b] + bOff;
        #pragma unroll
        for (int ks = 0; ks < 2; ks++) {
            const uint32_t kOfs = (uint32_t)(ks * 16 * 2);
            uint32_t a[2][4], br[4];
            ldm_x4(a[0], pA + kOfs);
            ldm_x4(a[1], pA + kOfs + 16 * PP * 2);
            ldm_x4(br, pB2 + kOfs);                 // n tiles 0,1 (klo/khi pairs)
            uint32_t bb0[2] = { br[0], br[1] };
            uint32_t bb1[2] = { br[2], br[3] };
            #pragma unroll
            for (int mt = 0; mt < 2; mt++) {
                mma16816(acc[mt][0], a[mt], bb0);
                mma16816(acc[mt][1], a[mt], bb1);
            }
        }
        __syncthreads();
    }
    sDen[pg][pr] = den;
    __syncthreads();

    #pragma unroll
    for (int mt = 0; mt < 2; mt++) {
        int r1 = wm + mt * 16 + gid;
        int r2 = r1 + 8;
        float inv1 = 1.f / (sDen[0][r1] + sDen[1][r1] + sDen[2][r1] + sDen[3][r1]);
        float inv2 = 1.f / (sDen[0][r2] + sDen[1][r2] + sDen[2][r2] + sDen[3][r2]);
        float* d1 = g_h + (size_t)(row0 + r1) * (HEADS * FH) + head * FH;
        float* d2 = g_h + (size_t)(row0 + r2) * (HEADS * FH) + head * FH;
        #pragma unroll
        for (int nt = 0; nt < 2; nt++) {
            int c = wn + nt * 8 + tig * 2;
            *(float2*)(d1 + c) = make_float2(acc[mt][nt][0] * inv1, acc[mt][nt][1] * inv1);
            *(float2*)(d2 + c) = make_float2(acc[mt][nt][2] * inv2, acc[mt][nt][3] * inv2);
        }
    }
}

// ---------------- K5: Who = h @ W_out (stored transposed fp16), s1o/s2o, max ----------------
__global__ void k5_outprep(const float* __restrict__ W_out,
                           const float* __restrict__ a_out) {
    int row0 = blockIdx.x * 64;
    __shared__ float sH[64][133];
    __shared__ float sWo[128][16];
    __shared__ float sA[32];
    __shared__ float sOut[64][17];
    __shared__ float sRed[2];
    int t = threadIdx.x;  // 256

    #pragma unroll
    for (int i = 0; i < 8; i++) {
        int q = t + 256 * i;
        int r = q >> 5, c = (q & 31) * 4;
        float4 v = *(const float4*)&g_h[(size_t)(row0 + r) * 128 + c];
        sH[r][c] = v.x; sH[r][c + 1] = v.y; sH[r][c + 2] = v.z; sH[r][c + 3] = v.w;
    }
    #pragma unroll
    for (int i = 0; i < 2; i++) {
        int q = t + 256 * i;
        int k = q >> 2, c = (q & 3) * 4;
        *(float4*)&sWo[k][c] = *(const float4*)&W_out[k * 16 + c];
    }
    if (t < 32) sA[t] = a_out[t];
    __syncthreads();

    int r = t & 63, cg = t >> 6;
    float4 a4 = make_float4(0.f, 0.f, 0.f, 0.f);
    for (int k = 0; k < 128; k++) {
        float hv = sH[r][k];
        float4 w4 = *(float4*)&sWo[k][cg * 4];
        a4.x += hv * w4.x; a4.y += hv * w4.y; a4.z += hv * w4.z; a4.w += hv * w4.w;
    }
    sOut[r][cg * 4 + 0] = a4.x; sOut[r][cg * 4 + 1] = a4.y;
    sOut[r][cg * 4 + 2] = a4.z; sOut[r][cg * 4 + 3] = a4.w;
    __syncthreads();

    if (t < 64) {
        int row = row0 + t;
        float s1 = 0.f, s2 = 0.f;
        #pragma unroll
        for (int c = 0; c < COUT; c++) {
            float v = sOut[t][c];
            s1 += v * sA[c];
            s2 += v * sA[COUT + c];
            g_WhoT[(size_t)c * N + row] = __float2half(v);
        }
        g_s1o[row] = s1;
        g_s2o[row] = s2;
        float m = s2;
        #pragma unroll
        for (int off = 16; off > 0; off >>= 1)
            m = fmaxf(m, __shfl_down_sync(0xFFFFFFFFu, m, off));
        if ((t & 31) == 0) sRed[t >> 5] = m;
    }
    __syncthreads();
    if (t == 0) atomicMaxF(&g_s2omax, fmaxf(sRed[0], sRed[1]));
}

// ---------------- K6: out-layer attention. BM=64, BN=16, 256 thr, grid 128 ----------------
__global__ void __launch_bounds__(256) k6_attn_tc(float* __restrict__ out) {
    const int row0 = blockIdx.x * 64;
    __shared__ __align__(16) __half sP[2][64 * PP];    // 2 x 5 KB
    __shared__ __align__(16) __half sB[2][16 * PP];    // 2 x 1.25 KB
    __shared__ float sS1[64], sM[64], sDen[4][64];
    __shared__ float sO[64][18];

    const int t = threadIdx.x;
    if (t < 64) {
        float v = g_s1o[row0 + t];
        sS1[t] = v;
        float e = v + g_s2omax;
        sM[t] = e > 0.f ? e : ALPHA * e;
    }
    __syncthreads();

    const int pr = t & 63, pg = t >> 6;
    const float* s2p = g_s2o + (pg << 3);
    const unsigned* mrow = g_mask + row0 + pr;
    const float s1v = sS1[pr], mv = sM[pr];
    float den = 0.f;

    // warps: 4(m) x 2(n); warp tile 16x8
    const int wid = t >> 5, lane = t & 31;
    const int wm = (wid & 3) * 16, wn = (wid >> 2) * 8;
    const int gid = lane >> 2, tig = lane & 3;
    float acc[4];
    #pragma unroll
    for (int c = 0; c < 4; c++) acc[c] = 0.f;

    const uint32_t aOff = (uint32_t)(((wm + (lane & 15)) * PP + ((lane >> 4) << 3)) * 2);
    // B x2: lanes 0-7 -> klo rows, 8-15 -> khi; others duplicate (ignored)
    const uint32_t bOff = (uint32_t)(((wn + (lane & 7)) * PP + (((lane >> 3) & 1) << 3)) * 2);
    const uint32_t pBase[2] = { smem_u32(sP[0]), smem_u32(sP[1]) };
    const uint32_t bBase[2] = { smem_u32(sB[0]), smem_u32(sB[1]) };

    const int bn = t >> 2, bk = (t & 3) * 8;   // t<64 stages B (16 rows x 32 halfs)
    const __half* bsrc = g_WhoT + (size_t)bn * N + bk;
    const bool bstage = (t < 64);

    unsigned mwR[2];
    float4   s2R[2][2];
    uint4    bR[2];
    #pragma unroll
    for (int s = 0; s < 2; s++) {
        mwR[s] = mrow[(size_t)s * N];
        s2R[s][0] = *(const float4*)(s2p + (s << 5));
        s2R[s][1] = *(const float4*)(s2p + (s << 5) + 4);
        if (bstage) bR[s] = *(const uint4*)(bsrc + (s << 5));
    }
    gen_p8(sP[0], pr, pg, mwR[0], s1v, mv, s2R[0], den);
    if (bstage) *(uint4*)(sB[0] + bn * PP + bk) = bR[0];
    __syncthreads();

    for (int kt = 0; kt < NW; kt++) {
        const int b = kt & 1;
        if (kt + 2 < NW) {
            const int j2 = (kt + 2) << 5;
            mwR[b] = mrow[(size_t)(kt + 2) * N];
            s2R[b][0] = *(const float4*)(s2p + j2);
            s2R[b][1] = *(const float4*)(s2p + j2 + 4);
            if (bstage) bR[b] = *(const uint4*)(bsrc + j2);
        }
        if (kt + 1 < NW) {
            gen_p8(sP[b ^ 1], pr, pg, mwR[b ^ 1], s1v, mv, s2R[b ^ 1], den);
            if (bstage) *(uint4*)(sB[b ^ 1] + bn * PP + bk) = bR[b ^ 1];
        }
        const uint32_t pA = pBase[b] + aOff;
        const uint32_t pB2 = bBase[b] + bOff;
        #pragma unroll
        for (int ks = 0; ks < 2; ks++) {
            const uint32_t kOfs = (uint32_t)(ks * 16 * 2);
            uint32_t a[4], br[2];
            ldm_x4(a, pA + kOfs);
            ldm_x2(br, pB2 + kOfs);
            mma16816(acc, a, br);
        }
        __syncthreads();
    }
    sDen[pg][pr] = den;
    __syncthreads();

    {
        int r1 = wm + gid, r2 = r1 + 8;
        float inv1 = 1.f / (sDen[0][r1] + sDen[1][r1] + sDen[2][r1] + sDen[3][r1]);
        float inv2 = 1.f / (sDen[0][r2] + sDen[1][r2] + sDen[2][r2] + sDen[3][r2]);
        int c = wn + tig * 2;
        sO[r1][c]     = acc[0] * inv1;
        sO[r1][c + 1] = acc[1] * inv1;
        sO[r2][c]     = acc[2] * inv2;
        sO[r2][c + 1] = acc[3] * inv2;
    }
    __syncthreads();

    if (t < 64) {
        float v[COUT];
        float m = -INFINITY;
        #pragma unroll
        for (int c = 0; c < COUT; c++) {
            float xv = sO[t][c];
            xv = xv > 0.f ? xv : (__expf(xv) - 1.f);   // elu
            v[c] = xv;
            m = fmaxf(m, xv);
        }
        float s = 0.f;
        #pragma unroll
        for (int c = 0; c < COUT; c++) s += __expf(v[c] - m);
        float lse = m + logf(s);
        float* dst = out + (size_t)(row0 + t) * COUT;
        #pragma unroll
        for (int c = 0; c < COUT; c += 4)
            *(float4*)(dst + c) = make_float4(v[c] - lse, v[c + 1] - lse,
                                              v[c + 2] - lse, v[c + 3] - lse);
    }
}

// ---------------- launch ----------------
extern "C" void kernel_launch(void* const* d_in, const int* in_sizes, int n_in,
                              void* d_out, int out_size) {
    const float* x       = (const float*)d_in[0];
    const int*   adj     = (const int*)d_in[1];
    const float* W_heads = (const float*)d_in[2];
    const float* a_heads = (const float*)d_in[3];
    const float* W_out   = (const float*)d_in[4];
    const float* a_out   = (const float*)d_in[5];
    float* out = (float*)d_out;

    k0_init<<<1, 1>>>();
    k1_pack<<<1024, 256>>>(adj);
    k2_wh<<<dim3(128, 2), 256>>>(x, W_heads, a_heads);
    k4_attn_tc<<<dim3(128, 2), 256>>>();
    k5_outprep<<<128, 256>>>(W_out, a_out);
    k6_attn_tc<<<128, 256>>>(out);
}

// round 9
// speedup vs baseline: 2.0770x; 1.6750x over previous
#include <cuda_runtime.h>
#include <cuda_fp16.h>
#include <math.h>
#include <cstdint>

#define N      8192
#define FH     64
#define HEADS  2
#define COUT   16
#define FIN    64
#define NW     256       // mask words per row (N/32)
#define NT     128       // k-tiles (N/64)
#define ALPHA  0.2f
#define PP     72        // smem pitch in halfs (144B; ldmatrix/STS conflict-free)

// ---------------- scratch ----------------
__device__ __align__(16) unsigned g_mask[NW * N];          // g_mask[w*N + i], bit b <-> col w*32+b
__device__ __align__(16) __half   g_WhT[HEADS][FH * N];    // transposed Wh (fp16): [f][row]
__device__ __align__(16) float    g_s1[HEADS][N];
__device__ __align__(16) float    g_s2[HEADS][N];
__device__               float    g_s2max[HEADS];
__device__ __align__(16) __half2  g_fB2[HEADS][N / 2];     // exp(s2 - s2max) pairs
__device__ __align__(16) __half2  g_fD2[HEADS][N / 2];     // exp(0.2(s2 - s2max)) pairs
__device__ __align__(16) float    g_h[(size_t)N * (HEADS * FH)];  // [N][128] fp32
__device__ __align__(16) __half   g_WhoT[COUT * N];        // transposed Who (fp16): [c][row]
__device__ __align__(16) float    g_s1o[N];
__device__ __align__(16) float    g_s2o[N];
__device__               float    g_s2omax;
__device__ __align__(16) __half2  g_fBo2[N / 2];
__device__ __align__(16) __half2  g_fDo2[N / 2];

__device__ __forceinline__ uint32_t smem_u32(const void* p) {
    return (uint32_t)__cvta_generic_to_shared(p);
}

__device__ __forceinline__ void mma16816(float* c, const uint32_t* a, const uint32_t* b) {
    asm volatile("mma.sync.aligned.m16n8k16.row.col.f32.f16.f16.f32 "
        "{%0,%1,%2,%3}, {%4,%5,%6,%7}, {%8,%9}, {%0,%1,%2,%3};"
        : "+f"(c[0]), "+f"(c[1]), "+f"(c[2]), "+f"(c[3])
        : "r"(a[0]), "r"(a[1]), "r"(a[2]), "r"(a[3]), "r"(b[0]), "r"(b[1]));
}

__device__ __forceinline__ void ldm_x4(uint32_t* r, uint32_t addr) {
    asm volatile("ldmatrix.sync.aligned.m8n8.x4.shared.b16 {%0,%1,%2,%3}, [%4];"
        : "=r"(r[0]), "=r"(r[1]), "=r"(r[2]), "=r"(r[3]) : "r"(addr));
}

__device__ __forceinline__ void ldm_x2(uint32_t* r, uint32_t addr) {
    asm volatile("ldmatrix.sync.aligned.m8n8.x2.shared.b16 {%0,%1}, [%2];"
        : "=r"(r[0]), "=r"(r[1]) : "r"(addr));
}

__device__ __forceinline__ float atomicMaxF(float* addr, float v) {
    int* ia = (int*)addr;
    int old = *ia;
    while (__int_as_float(old) < v) {
        int assumed = old;
        old = atomicCAS(ia, assumed, __float_as_int(v));
        if (old == assumed) break;
    }
    return __int_as_float(old);
}

__global__ void k0_init() {
    g_s2max[0] = -INFINITY;
    g_s2max[1] = -INFINITY;
    g_s2omax   = -INFINITY;
}

// ---------------- K1: pack adjacency into transposed bitmask (MLP=8) ----------------
__global__ void k1_pack(const int* __restrict__ adj) {
    int warp = (blockIdx.x * blockDim.x + threadIdx.x) >> 5;
    int lane = threadIdx.x & 31;
    if (warp >= N) return;
    const int* arow = adj + (size_t)warp * N;
    for (int w = 0; w < NW; w += 8) {
        int v[8];
        #pragma unroll
        for (int i = 0; i < 8; i++) v[i] = arow[(w + i) * 32 + lane];
        unsigned b[8];
        #pragma unroll
        for (int i = 0; i < 8; i++) b[i] = __ballot_sync(0xFFFFFFFFu, v[i] > 0);
        if (lane == 0) {
            #pragma unroll
            for (int i = 0; i < 8; i++) g_mask[(size_t)(w + i) * N + warp] = b[i];
        }
    }
}

// ---------------- K2: Wh = x @ W per head (transposed fp16), s1/s2, max(s2) ----------------
__global__ void k2_wh(const float* __restrict__ x,
                      const float* __restrict__ W_heads,
                      const float* __restrict__ a_heads) {
    int head = blockIdx.y;
    int row0 = blockIdx.x * 64;
    __shared__ float sX[64][65];
    __shared__ float sW[64][64];
    __shared__ float sA[2 * FH];
    __shared__ float sRed[2];
    int t = threadIdx.x;  // 256

    #pragma unroll
    for (int i = 0; i < 4; i++) {
        int q = t + 256 * i;
        int r = q >> 4, c = (q & 15) * 4;
        float4 v = *(const float4*)&x[(size_t)(row0 + r) * FIN + c];
        sX[r][c] = v.x; sX[r][c + 1] = v.y; sX[r][c + 2] = v.z; sX[r][c + 3] = v.w;
    }
    const float* W = W_heads + head * FIN * FH;
    #pragma unroll
    for (int i = 0; i < 4; i++) {
        int q = t + 256 * i;
        int r = q >> 4, c = (q & 15) * 4;
        *(float4*)&sW[r][c] = *(const float4*)&W[r * FH + c];
    }
    if (t < 2 * FH) sA[t] = a_heads[head * 2 * FH + t];
    __syncthreads();

    int r = t & 63, cg = t >> 6;
    float4 acc[4];
    #pragma unroll
    for (int j = 0; j < 4; j++) acc[j] = make_float4(0.f, 0.f, 0.f, 0.f);
    for (int k = 0; k < FIN; k++) {
        float xv = sX[r][k];
        #pragma unroll
        for (int j = 0; j < 4; j++) {
            float4 w4 = *(float4*)&sW[k][cg * 16 + j * 4];
            acc[j].x += xv * w4.x; acc[j].y += xv * w4.y;
            acc[j].z += xv * w4.z; acc[j].w += xv * w4.w;
        }
    }
    __syncthreads();
    #pragma unroll
    for (int j = 0; j < 4; j++) {
        sX[r][cg * 16 + j * 4 + 0] = acc[j].x;
        sX[r][cg * 16 + j * 4 + 1] = acc[j].y;
        sX[r][cg * 16 + j * 4 + 2] = acc[j].z;
        sX[r][cg * 16 + j * 4 + 3] = acc[j].w;
    }
    __syncthreads();

    if (t < 64) {
        int row = row0 + t;
        float s1 = 0.f, s2 = 0.f;
        float* o = sX[t];
        #pragma unroll
        for (int f = 0; f < FH; f++) {
            s1 += o[f] * sA[f];
            s2 += o[f] * sA[FH + f];
            g_WhT[head][(size_t)f * N + row] = __float2half(o[f]);
        }
        g_s1[head][row] = s1;
        g_s2[head][row] = s2;
        float m = s2;
        #pragma unroll
        for (int off = 16; off > 0; off >>= 1)
            m = fmaxf(m, __shfl_down_sync(0xFFFFFFFFu, m, off));
        if ((t & 31) == 0) sRed[t >> 5] = m;
    }
    __syncthreads();
    if (t == 0) atomicMaxF(&g_s2max[head], fmaxf(sRed[0], sRed[1]));
}

// ---------------- K3: per-column softmax factors B_j, D_j (heads) ----------------
__global__ void k3_factors() {
    int head = blockIdx.y;
    int j = (blockIdx.x * 256 + threadIdx.x) * 2;
    float m = g_s2max[head];
    float a = g_s2[head][j] - m, b = g_s2[head][j + 1] - m;
    g_fB2[head][j >> 1] = __floats2half2_rn(__expf(a), __expf(b));
    g_fD2[head][j >> 1] = __floats2half2_rn(__expf(ALPHA * a), __expf(ALPHA * b));
}

// ---------------- pair helper: p = mask & max(A*B, C*D) for 2 cols ----------------
__device__ __forceinline__ void p_pair(uint32_t A2, uint32_t C2, uint32_t bb, uint32_t dd,
                                       unsigned mw, int i2, uint32_t& outp, float& den) {
    __half2 a2 = *reinterpret_cast<const __half2*>(&A2);
    __half2 c2 = *reinterpret_cast<const __half2*>(&C2);
    __half2 bh = *reinterpret_cast<const __half2*>(&bb);
    __half2 dh = *reinterpret_cast<const __half2*>(&dd);
    __half2 pm = __hmax2(__hmul2(a2, bh), __hmul2(c2, dh));
    uint32_t msk = ((mw >> i2) & 1u) * 0xFFFFu + ((mw >> (i2 + 1)) & 1u) * 0xFFFF0000u;
    uint32_t pv = (*reinterpret_cast<uint32_t*>(&pm)) & msk;
    __half2 ph = *reinterpret_cast<const __half2*>(&pv);
    float2 f = __half22float2(ph);
    den += f.x + f.y;
    outp = pv;
}

// gen 16 cols (8 pairs) into sP row pr, col base pg*16; mw pre-shifted 16 bits.
__device__ __forceinline__ void gen16(__half* sPb, int pr, int pg, unsigned mw,
                                      uint32_t A2, uint32_t C2,
                                      const uint4& fB0, const uint4& fB1,
                                      const uint4& fD0, const uint4& fD1, float& den) {
    uint32_t o[8];
    p_pair(A2, C2, fB0.x, fD0.x, mw,  0, o[0], den);
    p_pair(A2, C2, fB0.y, fD0.y, mw,  2, o[1], den);
    p_pair(A2, C2, fB0.z, fD0.z, mw,  4, o[2], den);
    p_pair(A2, C2, fB0.w, fD0.w, mw,  6, o[3], den);
    p_pair(A2, C2, fB1.x, fD1.x, mw,  8, o[4], den);
    p_pair(A2, C2, fB1.y, fD1.y, mw, 10, o[5], den);
    p_pair(A2, C2, fB1.z, fD1.z, mw, 12, o[6], den);
    p_pair(A2, C2, fB1.w, fD1.w, mw, 14, o[7], den);
    uint4* dst = (uint4*)(sPb + pr * PP + pg * 16);
    dst[0] = make_uint4(o[0], o[1], o[2], o[3]);
    dst[1] = make_uint4(o[4], o[5], o[6], o[7]);
}

// ---------------- K4: fused attention GEMM. BM=64, BN=64, BK=64, 256 thr, grid (128,2) ----------------
__global__ void __launch_bounds__(256, 2) k4_attn_tc() {
    const int head = blockIdx.y;
    const int row0 = blockIdx.x * 64;
    __shared__ __align__(16) __half sP[2][64 * PP];    // 2 x 9 KB
    __shared__ __align__(16) __half sB[2][64 * PP];    // 2 x 9 KB
    __shared__ uint32_t sA2u[64], sC2u[64];
    __shared__ float sDen[4][64];

    const int t = threadIdx.x;
    if (t < 64) {
        float u = g_s1[head][row0 + t] + g_s2max[head];
        float mv = u > 0.f ? u : ALPHA * u;
        float A = __expf(u - mv);
        float C = __expf(ALPHA * u - mv);
        __half2 a2 = __floats2half2_rn(A, A);
        __half2 c2 = __floats2half2_rn(C, C);
        sA2u[t] = *reinterpret_cast<uint32_t*>(&a2);
        sC2u[t] = *reinterpret_cast<uint32_t*>(&c2);
    }
    __syncthreads();

    const int pr = t & 63, pg = t >> 6;         // 4 col-groups of 16
    const uint32_t A2 = sA2u[pr], C2 = sC2u[pr];
    const int mshift = (pg & 1) * 16;
    const unsigned* mbase = g_mask + (size_t)(pg >> 1) * N + row0 + pr;   // + 2*kt*N
    const uint4* fBp = (const uint4*)(g_fB2[head]) + pg * 2;              // + kt*8
    const uint4* fDp = (const uint4*)(g_fD2[head]) + pg * 2;
    const __half* whT = g_WhT[head];
    float den = 0.f;

    // warps: 2(m) x 4(n); warp tile 32x16
    const int wid = t >> 5, lane = t & 31;
    const int wm = (wid & 1) * 32, wn = (wid >> 1) * 16;
    const int gid = lane >> 2, tig = lane & 3;
    float acc[2][2][4];
    #pragma unroll
    for (int a = 0; a < 2; a++)
        #pragma unroll
        for (int b = 0; b < 2; b++)
            #pragma unroll
            for (int c = 0; c < 4; c++) acc[a][b][c] = 0.f;

    const uint32_t aOff = (uint32_t)(((wm + (lane & 15)) * PP + ((lane >> 4) << 3)) * 2);
    const uint32_t bOff = (uint32_t)(((wn + ((lane >> 4) << 3) + (lane & 7)) * PP + (((lane >> 3) & 1) << 3)) * 2);
    const uint32_t pBase[2] = { smem_u32(sP[0]), smem_u32(sP[1]) };
    const uint32_t bBase[2] = { smem_u32(sB[0]), smem_u32(sB[1]) };

    // B staging: 2 uint4/thread; q = t, t+256: n = q>>3, kk = (q&7)*8
    const int bn0 = t >> 3, bk0 = (t & 7) * 8;
    const int bn1 = (t + 256) >> 3, bk1 = bk0;
    const __half* bsrc0 = whT + (size_t)bn0 * N + bk0;
    const __half* bsrc1 = whT + (size_t)bn1 * N + bk1;
    __half* bdst0 = nullptr; __half* bdst1 = nullptr;   // set per buffer

    // prefetch slots (tile kt -> slot kt&1)
    unsigned mwR[2];
    uint4 fBR[2][2], fDR[2][2], bR[2][2];
    #pragma unroll
    for (int s = 0; s < 2; s++) {
        mwR[s] = mbase[(size_t)(2 * s) * N] >> mshift;
        fBR[s][0] = fBp[s * 8];     fBR[s][1] = fBp[s * 8 + 1];
        fDR[s][0] = fDp[s * 8];     fDR[s][1] = fDp[s * 8 + 1];
        bR[s][0] = *(const uint4*)(bsrc0 + s * 64);
        bR[s][1] = *(const uint4*)(bsrc1 + s * 64);
    }
    gen16(sP[0], pr, pg, mwR[0], A2, C2, fBR[0][0], fBR[0][1], fDR[0][0], fDR[0][1], den);
    *(uint4*)(sB[0] + bn0 * PP + bk0) = bR[0][0];
    *(uint4*)(sB[0] + bn1 * PP + bk1) = bR[0][1];
    __syncthreads();

    for (int kt = 0; kt < NT; kt++) {
        const int b = kt & 1;
        if (kt + 2 < NT) {
            const int k2 = kt + 2;
            mwR[b] = mbase[(size_t)(2 * k2) * N] >> mshift;
            fBR[b][0] = fBp[k2 * 8];     fBR[b][1] = fBp[k2 * 8 + 1];
            fDR[b][0] = fDp[k2 * 8];     fDR[b][1] = fDp[k2 * 8 + 1];
            bR[b][0] = *(const uint4*)(bsrc0 + k2 * 64);
            bR[b][1] = *(const uint4*)(bsrc1 + k2 * 64);
        }
        if (kt + 1 < NT) {
            const int o = b ^ 1;
            gen16(sP[o], pr, pg, mwR[o], A2, C2, fBR[o][0], fBR[o][1], fDR[o][0], fDR[o][1], den);
            *(uint4*)(sB[o] + bn0 * PP + bk0) = bR[o][0];
            *(uint4*)(sB[o] + bn1 * PP + bk1) = bR[o][1];
        }
        const uint32_t pA = pBase[b] + aOff;
        const uint32_t pB2 = bBase[b] + bOff;
        #pragma unroll
        for (int ks = 0; ks < 4; ks++) {
            const uint32_t kOfs = (uint32_t)(ks * 32);
            uint32_t a[2][4], br[4];
            ldm_x4(a[0], pA + kOfs);
            ldm_x4(a[1], pA + kOfs + 16 * PP * 2);
            ldm_x4(br, pB2 + kOfs);
            uint32_t bb0[2] = { br[0], br[1] };
            uint32_t bb1[2] = { br[2], br[3] };
            #pragma unroll
            for (int mt = 0; mt < 2; mt++) {
                mma16816(acc[mt][0], a[mt], bb0);
                mma16816(acc[mt][1], a[mt], bb1);
            }
        }
        __syncthreads();
    }
    sDen[pg][pr] = den;
    __syncthreads();

    #pragma unroll
    for (int mt = 0; mt < 2; mt++) {
        int r1 = wm + mt * 16 + gid;
        int r2 = r1 + 8;
        float inv1 = 1.f / (sDen[0][r1] + sDen[1][r1] + sDen[2][r1] + sDen[3][r1]);
        float inv2 = 1.f / (sDen[0][r2] + sDen[1][r2] + sDen[2][r2] + sDen[3][r2]);
        float* d1 = g_h + (size_t)(row0 + r1) * (HEADS * FH) + head * FH;
        float* d2 = g_h + (size_t)(row0 + r2) * (HEADS * FH) + head * FH;
        #pragma unroll
        for (int nt = 0; nt < 2; nt++) {
            int c = wn + nt * 8 + tig * 2;
            *(float2*)(d1 + c) = make_float2(acc[mt][nt][0] * inv1, acc[mt][nt][1] * inv1);
            *(float2*)(d2 + c) = make_float2(acc[mt][nt][2] * inv2, acc[mt][nt][3] * inv2);
        }
    }
}

// ---------------- K5: Who = h @ W_out (transposed fp16), s1o/s2o, max ----------------
__global__ void k5_outprep(const float* __restrict__ W_out,
                           const float* __restrict__ a_out) {
    int row0 = blockIdx.x * 64;
    __shared__ float sH[64][133];
    __shared__ float sWo[128][16];
    __shared__ float sA[32];
    __shared__ float sOut[64][17];
    __shared__ float sRed[2];
    int t = threadIdx.x;  // 256

    #pragma unroll
    for (int i = 0; i < 8; i++) {
        int q = t + 256 * i;
        int r = q >> 5, c = (q & 31) * 4;
        float4 v = *(const float4*)&g_h[(size_t)(row0 + r) * 128 + c];
        sH[r][c] = v.x; sH[r][c + 1] = v.y; sH[r][c + 2] = v.z; sH[r][c + 3] = v.w;
    }
    #pragma unroll
    for (int i = 0; i < 2; i++) {
        int q = t + 256 * i;
        int k = q >> 2, c = (q & 3) * 4;
        *(float4*)&sWo[k][c] = *(const float4*)&W_out[k * 16 + c];
    }
    if (t < 32) sA[t] = a_out[t];
    __syncthreads();

    int r = t & 63, cg = t >> 6;
    float4 a4 = make_float4(0.f, 0.f, 0.f, 0.f);
    for (int k = 0; k < 128; k++) {
        float hv = sH[r][k];
        float4 w4 = *(float4*)&sWo[k][cg * 4];
        a4.x += hv * w4.x; a4.y += hv * w4.y; a4.z += hv * w4.z; a4.w += hv * w4.w;
    }
    sOut[r][cg * 4 + 0] = a4.x; sOut[r][cg * 4 + 1] = a4.y;
    sOut[r][cg * 4 + 2] = a4.z; sOut[r][cg * 4 + 3] = a4.w;
    __syncthreads();

    if (t < 64) {
        int row = row0 + t;
        float s1 = 0.f, s2 = 0.f;
        #pragma unroll
        for (int c = 0; c < COUT; c++) {
            float v = sOut[t][c];
            s1 += v * sA[c];
            s2 += v * sA[COUT + c];
            g_WhoT[(size_t)c * N + row] = __float2half(v);
        }
        g_s1o[row] = s1;
        g_s2o[row] = s2;
        float m = s2;
        #pragma unroll
        for (int off = 16; off > 0; off >>= 1)
            m = fmaxf(m, __shfl_down_sync(0xFFFFFFFFu, m, off));
        if ((t & 31) == 0) sRed[t >> 5] = m;
    }
    __syncthreads();
    if (t == 0) atomicMaxF(&g_s2omax, fmaxf(sRed[0], sRed[1]));
}

// ---------------- K5f: out-layer factors ----------------
__global__ void k5f_factors() {
    int j = (blockIdx.x * 256 + threadIdx.x) * 2;
    float m = g_s2omax;
    float a = g_s1o ? (g_s2o[j] - m) : 0.f;   // keep compiler honest
    float b = g_s2o[j + 1] - m;
    g_fBo2[j >> 1] = __floats2half2_rn(__expf(a), __expf(b));
    g_fDo2[j >> 1] = __floats2half2_rn(__expf(ALPHA * a), __expf(ALPHA * b));
}

// ---------------- K6: out-layer attention. BM=64, BN=16, BK=64, 256 thr, grid 128 ----------------
__global__ void __launch_bounds__(256, 2) k6_attn_tc(float* __restrict__ out) {
    const int row0 = blockIdx.x * 64;
    __shared__ __align__(16) __half sP[2][64 * PP];    // 2 x 9 KB
    __shared__ __align__(16) __half sB[2][16 * PP];    // 2 x 2.25 KB
    __shared__ uint32_t sA2u[64], sC2u[64];
    __shared__ float sDen[4][64];
    __shared__ float sO[64][18];

    const int t = threadIdx.x;
    if (t < 64) {
        float u = g_s1o[row0 + t] + g_s2omax;
        float mv = u > 0.f ? u : ALPHA * u;
        float A = __expf(u - mv);
        float C = __expf(ALPHA * u - mv);
        __half2 a2 = __floats2half2_rn(A, A);
        __half2 c2 = __floats2half2_rn(C, C);
        sA2u[t] = *reinterpret_cast<uint32_t*>(&a2);
        sC2u[t] = *reinterpret_cast<uint32_t*>(&c2);
    }
    __syncthreads();

    const int pr = t & 63, pg = t >> 6;
    const uint32_t A2 = sA2u[pr], C2 = sC2u[pr];
    const int mshift = (pg & 1) * 16;
    const unsigned* mbase = g_mask + (size_t)(pg >> 1) * N + row0 + pr;
    const uint4* fBp = (const uint4*)(g_fBo2) + pg * 2;
    const uint4* fDp = (const uint4*)(g_fDo2) + pg * 2;
    float den = 0.f;

    // warps: 4(m) x 2(n); warp tile 16x8
    const int wid = t >> 5, lane = t & 31;
    const int wm = (wid & 3) * 16, wn = (wid >> 2) * 8;
    const int gid = lane >> 2, tig = lane & 3;
    float acc[4];
    #pragma unroll
    for (int c = 0; c < 4; c++) acc[c] = 0.f;

    const uint32_t aOff = (uint32_t)(((wm + (lane & 15)) * PP + ((lane >> 4) << 3)) * 2);
    const uint32_t bOff = (uint32_t)(((wn + (lane & 7)) * PP + (((lane >> 3) & 1) << 3)) * 2);
    const uint32_t pBase[2] = { smem_u32(sP[0]), smem_u32(sP[1]) };
    const uint32_t bBase[2] = { smem_u32(sB[0]), smem_u32(sB[1]) };

    // B staging: t<128 stage 1 uint4: n = t>>3 (0..15), kk = (t&7)*8
    const int bn = t >> 3, bk = (t & 7) * 8;
    const __half* bsrc = g_WhoT + (size_t)bn * N + bk;
    const bool bstage = (t < 128);

    unsigned mwR[2];
    uint4 fBR[2][2], fDR[2][2], bR[2];
    #pragma unroll
    for (int s = 0; s < 2; s++) {
        mwR[s] = mbase[(size_t)(2 * s) * N] >> mshift;
        fBR[s][0] = fBp[s * 8];     fBR[s][1] = fBp[s * 8 + 1];
        fDR[s][0] = fDp[s * 8];     fDR[s][1] = fDp[s * 8 + 1];
        if (bstage) bR[s] = *(const uint4*)(bsrc + s * 64);
    }
    gen16(sP[0], pr, pg, mwR[0], A2, C2, fBR[0][0], fBR[0][1], fDR[0][0], fDR[0][1], den);
    if (bstage) *(uint4*)(sB[0] + bn * PP + bk) = bR[0];
    __syncthreads();

    for (int kt = 0; kt < NT; kt++) {
        const int b = kt & 1;
        if (kt + 2 < NT) {
            const int k2 = kt + 2;
            mwR[b] = mbase[(size_t)(2 * k2) * N] >> mshift;
            fBR[b][0] = fBp[k2 * 8];     fBR[b][1] = fBp[k2 * 8 + 1];
            fDR[b][0] = fDp[k2 * 8];     fDR[b][1] = fDp[k2 * 8 + 1];
            if (bstage) bR[b] = *(const uint4*)(bsrc + k2 * 64);
        }
        if (kt + 1 < NT) {
            const int o = b ^ 1;
            gen16(sP[o], pr, pg, mwR[o], A2, C2, fBR[o][0], fBR[o][1], fDR[o][0], fDR[o][1], den);
            if (bstage) *(uint4*)(sB[o] + bn * PP + bk) = bR[o];
        }
        const uint32_t pA = pBase[b] + aOff;
        const uint32_t pB2 = bBase[b] + bOff;
        #pragma unroll
        for (int ks = 0; ks < 4; ks++) {
            const uint32_t kOfs = (uint32_t)(ks * 32);
            uint32_t a[4], br[2];
            ldm_x4(a, pA + kOfs);
            ldm_x2(br, pB2 + kOfs);
            mma16816(acc, a, br);
        }
        __syncthreads();
    }
    sDen[pg][pr] = den;
    __syncthreads();

    {
        int r1 = wm + gid, r2 = r1 + 8;
        float inv1 = 1.f / (sDen[0][r1] + sDen[1][r1] + sDen[2][r1] + sDen[3][r1]);
        float inv2 = 1.f / (sDen[0][r2] + sDen[1][r2] + sDen[2][r2] + sDen[3][r2]);
        int c = wn + tig * 2;
        sO[r1][c]     = acc[0] * inv1;
        sO[r1][c + 1] = acc[1] * inv1;
        sO[r2][c]     = acc[2] * inv2;
        sO[r2][c + 1] = acc[3] * inv2;
    }
    __syncthreads();

    if (t < 64) {
        float v[COUT];
        float m = -INFINITY;
        #pragma unroll
        for (int c = 0; c < COUT; c++) {
            float xv = sO[t][c];
            xv = xv > 0.f ? xv : (__expf(xv) - 1.f);   // elu
            v[c] = xv;
            m = fmaxf(m, xv);
        }
        float s = 0.f;
        #pragma unroll
        for (int c = 0; c < COUT; c++) s += __expf(v[c] - m);
        float lse = m + logf(s);
        float* dst = out + (size_t)(row0 + t) * COUT;
        #pragma unroll
        for (int c = 0; c < COUT; c += 4)
            *(float4*)(dst + c) = make_float4(v[c] - lse, v[c + 1] - lse,
                                              v[c + 2] - lse, v[c + 3] - lse);
    }
}

// ---------------- launch ----------------
extern "C" void kernel_launch(void* const* d_in, const int* in_sizes, int n_in,
                              void* d_out, int out_size) {
    const float* x       = (const float*)d_in[0];
    const int*   adj     = (const int*)d_in[1];
    const float* W_heads = (const float*)d_in[2];
    const float* a_heads = (const float*)d_in[3];
    const float* W_out   = (const float*)d_in[4];
    const float* a_out   = (const float*)d_in[5];
    float* out = (float*)d_out;

    k0_init<<<1, 1>>>();
    k1_pack<<<1024, 256>>>(adj);
    k2_wh<<<dim3(128, 2), 256>>>(x, W_heads, a_heads);
    k3_factors<<<dim3(16, 2), 256>>>();
    k4_attn_tc<<<dim3(128, 2), 256>>>();
    k5_outprep<<<128, 256>>>(W_out, a_out);
    k5f_factors<<<16, 256>>>();
    k6_attn_tc<<<128, 256>>>(out);
}